// round 11
// baseline (speedup 1.0000x reference)
#include <cuda_runtime.h>
#include <cuda_bf16.h>
#include <math.h>

#define N_NODES 100000
#define N_EDGES 1600000
#define IN_DIM  512
#define HID     64
#define OUTD    32

// ---------------- scratch (static device globals; no allocation) ----------------
__device__ int   g_deg[N_NODES];
__device__ float g_dinv[N_NODES];
__device__ int   g_off[N_NODES + 1];
__device__ int   g_cur[N_NODES];
__device__ int   g_srcs[N_EDGES];
__device__ float g_wgt[N_EDGES];
__device__ __nv_bfloat16 g_h1b[(size_t)N_NODES * HID];   // 12.8 MB, row = 128B
__device__ __nv_bfloat16 g_h2b[(size_t)N_NODES * OUTD];  // 6.4 MB,  row = 64B
__device__ int   g_bsum[256];
__device__ int   g_is64;

// W1 pre-packed into per-lane mma fragments:
// [chunk][ (ks*8+nt)*32 + lane ] = {bh0, bh1, bl0, bl1}
__device__ uint4 g_w1p[8][1024];   // 128 KB

__device__ __forceinline__ int load_edge(const void* ei, int part, int e) {
    if (g_is64) return (int)((const long long*)ei)[(size_t)part * N_EDGES + e];
    return ((const int*)ei)[(size_t)part * N_EDGES + e];
}

__device__ __forceinline__ unsigned hi16(float f) {
    return __float_as_uint(f) >> 16;
}
__device__ __forceinline__ unsigned lo16(float f) {
    float hf = __uint_as_float(__float_as_uint(f) & 0xFFFF0000u);
    return __float_as_uint(f - hf) >> 16;
}

// ---------------- init: degree=1 + W1 fragment pre-pack + int64/int32 detect ----------------
__global__ void k_init(const float* __restrict__ W1, const long long* __restrict__ ei) {
    int v = blockIdx.x * blockDim.x + threadIdx.x;
    if (v < N_NODES) g_deg[v] = 1;  // self-loop
    if (v < 8192) {
        int lane = v & 31, nt = (v >> 5) & 7, ks = (v >> 8) & 3, chunk = v >> 10;
        int q = lane & 3, lr = lane >> 2;
        int n = nt * 8 + lr;
        int k0 = chunk * 64 + ks * 16 + 2 * q;
        float w00 = W1[(size_t)k0 * 64 + n];
        float w01 = W1[(size_t)(k0 + 1) * 64 + n];
        float w10 = W1[(size_t)(k0 + 8) * 64 + n];
        float w11 = W1[(size_t)(k0 + 9) * 64 + n];
        uint4 f;
        f.x = hi16(w00) | (hi16(w01) << 16);
        f.y = hi16(w10) | (hi16(w11) << 16);
        f.z = lo16(w00) | (lo16(w01) << 16);
        f.w = lo16(w10) | (lo16(w11) << 16);
        g_w1p[chunk][(ks * 8 + nt) * 32 + lane] = f;
    }
    if (blockIdx.x == 0) {  // dtype detection
        __shared__ int ok;
        if (threadIdx.x == 0) ok = 1;
        __syncthreads();
        for (int j = threadIdx.x; j < 2048; j += blockDim.x) {
            long long e = ei[j];
            if (e < 0 || e >= N_NODES) atomicExch(&ok, 0);
        }
        __syncthreads();
        if (threadIdx.x == 0) g_is64 = ok;
    }
}

__global__ void k_hist(const void* __restrict__ ei) {
    int e = blockIdx.x * blockDim.x + threadIdx.x;
    if (e < N_EDGES) atomicAdd(&g_deg[load_edge(ei, 1, e)], 1);
}

// ---------------- GEMM1: h1 = x @ W1; 256thr/CTA, one m16 tile per warp ----------------
#define BMG 128

__device__ __forceinline__ void mma16816(float* c, const unsigned* a, const unsigned* b) {
    asm volatile(
        "mma.sync.aligned.m16n8k16.row.col.f32.bf16.bf16.f32 "
        "{%0,%1,%2,%3}, {%4,%5,%6,%7}, {%8,%9}, {%0,%1,%2,%3};\n"
        : "+f"(c[0]), "+f"(c[1]), "+f"(c[2]), "+f"(c[3])
        : "r"(a[0]), "r"(a[1]), "r"(a[2]), "r"(a[3]), "r"(b[0]), "r"(b[1]));
}

__device__ __forceinline__ unsigned hi_pack(float2 v) {
    return __byte_perm(__float_as_uint(v.x), __float_as_uint(v.y), 0x7632);
}
__device__ __forceinline__ unsigned lo_pack(float2 v) {
    unsigned bx = __float_as_uint(v.x), by = __float_as_uint(v.y);
    float lx = v.x - __uint_as_float(bx & 0xFFFF0000u);
    float ly = v.y - __uint_as_float(by & 0xFFFF0000u);
    return __byte_perm(__float_as_uint(lx), __float_as_uint(ly), 0x7632);
}
__device__ __forceinline__ unsigned pack_bf16x2(float lo, float hi) {
    unsigned r;
    asm("cvt.rn.bf16x2.f32 %0, %1, %2;" : "=r"(r) : "f"(hi), "f"(lo));
    return r;
}

__global__ __launch_bounds__(256, 3) void k_gemm1(const float* __restrict__ x) {
    __shared__ uint4 Bp[1024];  // 16 KB fragment-packed W1 chunk

    const int t = threadIdx.x;
    const int warp = t >> 5, lane = t & 31;
    const int q = lane & 3, lr = lane >> 2;
    const int rbase = blockIdx.x * BMG + warp * 16;

    const int r0 = rbase + lr, r1 = rbase + lr + 8;
    const bool v0 = r0 < N_NODES, v1 = r1 < N_NODES;
    const float* xp0 = x + (size_t)(v0 ? r0 : 0) * IN_DIM;
    const float* xp1 = x + (size_t)(v1 ? r1 : 0) * IN_DIM;

    float acc[8][4];
#pragma unroll
    for (int n = 0; n < 8; n++)
#pragma unroll
        for (int j = 0; j < 4; j++) acc[n][j] = 0.f;

    float2 vc[4], vn[4];
    const int c0 = 2 * q;
    const float2 z2 = make_float2(0.f, 0.f);

    vc[0] = v0 ? __ldcs((const float2*)(xp0 + c0))     : z2;
    vc[1] = v0 ? __ldcs((const float2*)(xp0 + c0 + 8)) : z2;
    vc[2] = v1 ? __ldcs((const float2*)(xp1 + c0))     : z2;
    vc[3] = v1 ? __ldcs((const float2*)(xp1 + c0 + 8)) : z2;

    for (int kt = 0; kt < IN_DIM; kt += 64) {
        __syncthreads();
        {
            const uint4* src = g_w1p[kt >> 6];
#pragma unroll
            for (int i = 0; i < 4; i++) Bp[t + 256 * i] = src[t + 256 * i];
        }
        __syncthreads();

#pragma unroll
        for (int ks = 0; ks < 4; ks++) {
            int knext = kt + ks * 16 + 16;
            if (knext < IN_DIM) {
                vn[0] = v0 ? __ldcs((const float2*)(xp0 + knext + c0))     : z2;
                vn[1] = v0 ? __ldcs((const float2*)(xp0 + knext + c0 + 8)) : z2;
                vn[2] = v1 ? __ldcs((const float2*)(xp1 + knext + c0))     : z2;
                vn[3] = v1 ? __ldcs((const float2*)(xp1 + knext + c0 + 8)) : z2;
            }
            unsigned ah[4], al[4];
            ah[0] = hi_pack(vc[0]); ah[1] = hi_pack(vc[2]);
            ah[2] = hi_pack(vc[1]); ah[3] = hi_pack(vc[3]);
            al[0] = lo_pack(vc[0]); al[1] = lo_pack(vc[2]);
            al[2] = lo_pack(vc[1]); al[3] = lo_pack(vc[3]);

#pragma unroll
            for (int nt = 0; nt < 8; nt++) {
                uint4 f = Bp[(ks * 8 + nt) * 32 + lane];  // one LDS.128
                unsigned bh[2] = {f.x, f.y};
                unsigned bl[2] = {f.z, f.w};
                mma16816(acc[nt], ah, bh);
                mma16816(acc[nt], ah, bl);
                mma16816(acc[nt], al, bh);
            }
#pragma unroll
            for (int i = 0; i < 4; i++) vc[i] = vn[i];
        }
    }

    // epilogue: pack bf16 pairs (one cvt.rn.bf16x2 per 2 elems; low volume)
#pragma unroll
    for (int nt = 0; nt < 8; nt++) {
        int col = nt * 8 + 2 * q;
        if (v0)
            *(unsigned*)&g_h1b[(size_t)r0 * HID + col] = pack_bf16x2(acc[nt][0], acc[nt][1]);
        if (v1)
            *(unsigned*)&g_h1b[(size_t)r1 * HID + col] = pack_bf16x2(acc[nt][2], acc[nt][3]);
    }
}

// ---------------- exclusive scan of (deg-1) to build CSR offsets ----------------
__global__ void k_scan1() {
    __shared__ int s[512];
    int t = threadIdx.x;
    int v = blockIdx.x * 512 + t;
    int c = (v < N_NODES) ? (g_deg[v] - 1) : 0;
    s[t] = c;
    __syncthreads();
    for (int o = 1; o < 512; o <<= 1) {
        int val = (t >= o) ? s[t - o] : 0;
        __syncthreads();
        s[t] += val;
        __syncthreads();
    }
    if (v < N_NODES) g_off[v] = s[t] - c;
    if (t == 511) g_bsum[blockIdx.x] = s[511];
}

__global__ void k_scan2(int nb) {
    __shared__ int s[256];
    int t = threadIdx.x;
    int c = (t < nb) ? g_bsum[t] : 0;
    s[t] = c;
    __syncthreads();
    for (int o = 1; o < 256; o <<= 1) {
        int val = (t >= o) ? s[t - o] : 0;
        __syncthreads();
        s[t] += val;
        __syncthreads();
    }
    if (t < nb) g_bsum[t] = s[t] - c;
}

__global__ void k_scan3() {
    int v = blockIdx.x * blockDim.x + threadIdx.x;
    if (v < N_NODES) {
        int o = g_off[v] + g_bsum[v >> 9];
        g_off[v] = o;
        g_cur[v] = o;
        g_dinv[v] = rsqrtf((float)g_deg[v]);
    }
    if (v == 0) g_off[N_NODES] = N_EDGES;
}

__global__ void k_scatter(const void* __restrict__ ei) {
    int e = blockIdx.x * blockDim.x + threadIdx.x;
    if (e < N_EDGES) {
        int d = load_edge(ei, 1, e);
        int s = load_edge(ei, 0, e);
        int pos = atomicAdd(&g_cur[d], 1);
        g_srcs[pos] = s;
        g_wgt[pos] = g_dinv[s] * g_dinv[d];
    }
}

// accumulate 8 bf16 channels from a uint4 — pure SHF/LOP3/FFMA, no convert pipe
__device__ __forceinline__ void acc8b(float* a, uint4 qv, float wg) {
    unsigned u[4] = {qv.x, qv.y, qv.z, qv.w};
#pragma unroll
    for (int i = 0; i < 4; i++) {
        float f0 = __uint_as_float(u[i] << 16);           // low bf16
        float f1 = __uint_as_float(u[i] & 0xFFFF0000u);   // high bf16
        a[2 * i]     = fmaf(wg, f0, a[2 * i]);
        a[2 * i + 1] = fmaf(wg, f1, a[2 * i + 1]);
    }
}

// ---------------- agg1: 4 edge-streams x 8 lanes x uint4 (bf16 h1) ----------------
__global__ __launch_bounds__(256) void k_agg1(const float* __restrict__ b1,
                                              const float* __restrict__ W2) {
    __shared__ float W2s[HID * OUTD];
    __shared__ float b1s[HID];
    __shared__ float ha[8][HID];
    int tid = threadIdx.x;
    for (int i = tid; i < HID * OUTD; i += 256) W2s[i] = W2[i];
    if (tid < HID) b1s[tid] = b1[tid];
    __syncthreads();

    int w = tid >> 5, lane = tid & 31;
    int v = blockIdx.x * 8 + w;
    if (v >= N_NODES) return;

    int sub = lane >> 3, j = lane & 7;
    const uint4* __restrict__ H = (const uint4*)g_h1b;  // 8 uint4 per row

    float a[8];
#pragma unroll
    for (int i = 0; i < 8; i++) a[i] = 0.f;

    float dv = g_dinv[v];
    if (sub == 0) acc8b(a, H[(size_t)v * 8 + j], dv * dv);  // self loop

    int e = g_off[v] + sub, end = g_off[v + 1];
    for (; e + 4 < end; e += 8) {  // 2 edges per stream in flight
        int s0 = g_srcs[e], s1 = g_srcs[e + 4];
        float w0 = g_wgt[e], w1 = g_wgt[e + 4];
        uint4 p0 = H[(size_t)s0 * 8 + j];
        uint4 p1 = H[(size_t)s1 * 8 + j];
        acc8b(a, p0, w0);
        acc8b(a, p1, w1);
    }
    if (e < end) acc8b(a, H[(size_t)g_srcs[e] * 8 + j], g_wgt[e]);

    // reduce the 4 streams
#pragma unroll
    for (int i = 0; i < 8; i++) {
        a[i] += __shfl_xor_sync(0xffffffffu, a[i], 8);
        a[i] += __shfl_xor_sync(0xffffffffu, a[i], 16);
    }

    if (sub == 0) {
#pragma unroll
        for (int i = 0; i < 8; i++)
            ha[w][8 * j + i] = fmaxf(a[i] + b1s[8 * j + i], 0.f);
    }
    __syncwarp();

    // layer-2 GEMV: col = lane; store bf16
    float acc = 0.f;
#pragma unroll
    for (int k = 0; k < HID; k++) acc = fmaf(ha[w][k], W2s[k * OUTD + lane], acc);
    g_h2b[(size_t)v * OUTD + lane] = __float2bfloat16_rn(acc);
}

// ---------------- agg2: 8 edge-streams x 4 lanes x uint4 (bf16 h2) + log_softmax ----
__global__ __launch_bounds__(256) void k_agg2(const float* __restrict__ b2,
                                              float* __restrict__ out) {
    int tid = threadIdx.x;
    int w = tid >> 5, lane = tid & 31;
    int v = blockIdx.x * 8 + w;
    if (v >= N_NODES) return;

    int sub = lane >> 2, j = lane & 3;
    const uint4* __restrict__ H = (const uint4*)g_h2b;  // 4 uint4 per row

    float a[8];
#pragma unroll
    for (int i = 0; i < 8; i++) a[i] = 0.f;

    float dv = g_dinv[v];
    if (sub == 0) acc8b(a, H[(size_t)v * 4 + j], dv * dv);

    int e = g_off[v] + sub, end = g_off[v + 1];
    for (; e < end; e += 8) acc8b(a, H[(size_t)g_srcs[e] * 4 + j], g_wgt[e]);

#pragma unroll
    for (int i = 0; i < 8; i++) {
        a[i] += __shfl_xor_sync(0xffffffffu, a[i], 4);
        a[i] += __shfl_xor_sync(0xffffffffu, a[i], 8);
        a[i] += __shfl_xor_sync(0xffffffffu, a[i], 16);
    }
#pragma unroll
    for (int i = 0; i < 8; i++) a[i] += b2[8 * j + i];

    float m = a[0];
#pragma unroll
    for (int i = 1; i < 8; i++) m = fmaxf(m, a[i]);
    m = fmaxf(m, __shfl_xor_sync(0xffffffffu, m, 1));
    m = fmaxf(m, __shfl_xor_sync(0xffffffffu, m, 2));
    float s = 0.f;
#pragma unroll
    for (int i = 0; i < 8; i++) s += expf(a[i] - m);
    s += __shfl_xor_sync(0xffffffffu, s, 1);
    s += __shfl_xor_sync(0xffffffffu, s, 2);
    float ls = m + logf(s);

    if (sub == 0) {
        float4 o0 = make_float4(a[0] - ls, a[1] - ls, a[2] - ls, a[3] - ls);
        float4 o1 = make_float4(a[4] - ls, a[5] - ls, a[6] - ls, a[7] - ls);
        *(float4*)&out[(size_t)v * OUTD + 8 * j]     = o0;
        *(float4*)&out[(size_t)v * OUTD + 8 * j + 4] = o1;
    }
}

// ---------------- launch: fork gemm1 onto a side stream to overlap preproc ----------------
extern "C" void kernel_launch(void* const* d_in, const int* in_sizes, int n_in,
                              void* d_out, int out_size) {
    const float* x  = (const float*)d_in[0];
    const void*  ei = d_in[1];
    const float* W1 = (const float*)d_in[2];
    const float* b1 = (const float*)d_in[3];
    const float* W2 = (const float*)d_in[4];
    const float* b2 = (const float*)d_in[5];
    float* out = (float*)d_out;

    static cudaStream_t s2;
    static cudaEvent_t evA, evB;
    static bool ready = false;
    if (!ready) {  // handle caching only; identical work every call
        cudaStreamCreateWithFlags(&s2, cudaStreamNonBlocking);
        cudaEventCreateWithFlags(&evA, cudaEventDisableTiming);
        cudaEventCreateWithFlags(&evB, cudaEventDisableTiming);
        ready = true;
    }

    // (1) init: deg=1, W1 fragment pre-pack, dtype detect
    k_init<<<(N_NODES + 255) / 256, 256>>>(W1, (const long long*)ei);
    cudaEventRecord(evA, 0);
    cudaStreamWaitEvent(s2, evA, 0);

    // main-stream edge pipeline
    k_hist<<<(N_EDGES + 255) / 256, 256>>>(ei);
    int nb = (N_NODES + 511) / 512;
    k_scan1<<<nb, 512>>>();

    // (4) gemm1 on side stream — overlaps the edge pipeline
    k_gemm1<<<(N_NODES + BMG - 1) / BMG, 256, 0, s2>>>(x);
    cudaEventRecord(evB, s2);

    k_scan2<<<1, 256>>>(nb);
    k_scan3<<<(N_NODES + 255) / 256, 256>>>();
    k_scatter<<<(N_EDGES + 255) / 256, 256>>>(ei);

    // join: aggs need both gemm1 (h1) and the edge pipeline
    cudaStreamWaitEvent(0, evB, 0);
    k_agg1<<<(N_NODES + 7) / 8, 256>>>(b1, W2);
    k_agg2<<<(N_NODES + 7) / 8, 256>>>(b2, out);
}